// round 16
// baseline (speedup 1.0000x reference)
#include <cuda_runtime.h>
#include <cuda_bf16.h>
#include <cuda_fp16.h>
#include <cstddef>

// ---------------- scratch (device globals; no allocation allowed) ----------
__device__ __half g_actA[33554432];               // mix/l1 outputs fp16 (NHWC)
__device__ __half g_actB[16777216];               // mix outputs fp16 (NHWC)
__device__ __half g_dwF[8388608];                 // dwconv out fp16 (M x K)
__device__ __half g_wspH[434176];                 // split mixer weights hi (N x K)
__device__ __half g_wspL[434176];                 // split mixer weights lo
__device__ float g_kern[1179648];                 // all 5 dyn kernel sets
__device__ float g_sums[2048];                    // per-layer sum/sumsq regions

// dyn-kernel region offsets (floats)
#define KOFF1 0
#define KOFF2 6144
#define KOFF3 137216
#define KOFF4 284672
#define KOFF5 808960
// BN sums region offsets
#define SOFF1 0
#define SOFF2 128
#define SOFF3 384
#define SOFF4 896
// split-weight region offsets (elements, N x K layout)
#define W2OFF 0
#define W3OFF 8192
#define W4OFF 40960
#define W5OFF 172032

// ---------------- helpers ----------------------------------------------------
__device__ __forceinline__ void mma_f16(float* c, unsigned a0, unsigned a1, unsigned a2,
                                        unsigned a3, unsigned b0, unsigned b1)
{
    asm volatile(
        "mma.sync.aligned.m16n8k16.row.col.f32.f16.f16.f32 "
        "{%0,%1,%2,%3}, {%4,%5,%6,%7}, {%8,%9}, {%0,%1,%2,%3};\n"
        : "+f"(c[0]), "+f"(c[1]), "+f"(c[2]), "+f"(c[3])
        : "r"(a0), "r"(a1), "r"(a2), "r"(a3), "r"(b0), "r"(b1));
}

__device__ __forceinline__ void cp16(void* dst, const void* src)
{
    unsigned d = (unsigned)__cvta_generic_to_shared(dst);
    asm volatile("cp.async.cg.shared.global [%0], [%1], 16;\n" :: "r"(d), "l"(src));
}
#define CP_COMMIT() asm volatile("cp.async.commit_group;\n" ::: "memory")
#define CP_WAIT(n)  asm volatile("cp.async.wait_group %0;\n" :: "n"(n) : "memory")

// ---------------- prep: all dyn kernels (tanh(e@W+b)) + zero sums -----------
__global__ void prep_kernel(const int* __restrict__ label, const float* __restrict__ emb,
                            const float* __restrict__ w1, const float* __restrict__ b1,
                            const float* __restrict__ w2, const float* __restrict__ b2,
                            const float* __restrict__ w3, const float* __restrict__ b3,
                            const float* __restrict__ w4, const float* __restrict__ b4,
                            const float* __restrict__ w5, const float* __restrict__ b5,
                            float* __restrict__ kern, float* __restrict__ sums)
{
    int b = blockIdx.y;
    int i = blockIdx.x * 256 + threadIdx.x;
    if (b == 0 && i < 1920) sums[i] = 0.f;

    const float* W; const float* bb; int ck, off, j;
    if (i < 48)            { W = w1; bb = b1; ck = 48;   off = KOFF1; j = i; }
    else if (i < 1072)     { W = w2; bb = b2; ck = 1024; off = KOFF2; j = i - 48; }
    else if (i < 2224)     { W = w3; bb = b3; ck = 1152; off = KOFF3; j = i - 1072; }
    else if (i < 6320)     { W = w4; bb = b4; ck = 4096; off = KOFF4; j = i - 2224; }
    else if (i < 8368)     { W = w5; bb = b5; ck = 2048; off = KOFF5; j = i - 6320; }
    else return;

    const float* e = emb + label[b] * 5;
    float a = bb[j];
#pragma unroll
    for (int t = 0; t < 5; t++) a += e[t] * W[t * ck + j];
    kern[off + (size_t)b * ck + j] = tanhf(a);
}

// ---------------- wsplit: mixer weights fp32 (K x N) -> fp16 hi/lo (N x K) --
__global__ void wsplit_kernel(const float* __restrict__ w2, const float* __restrict__ w3,
                              const float* __restrict__ w4, const float* __restrict__ w5,
                              __half* __restrict__ wh, __half* __restrict__ wl)
{
    int i = blockIdx.x * 256 + threadIdx.x;
    const float* W; int K, N, off, j;
    if (i < 8192)        { W = w2; K = 64;  N = 128; off = W2OFF; j = i; }
    else if (i < 40960)  { W = w3; K = 128; N = 256; off = W3OFF; j = i - 8192; }
    else if (i < 172032) { W = w4; K = 256; N = 512; off = W4OFF; j = i - 40960; }
    else if (i < 434176) { W = w5; K = 512; N = 512; off = W5OFF; j = i - 172032; }
    else return;
    int n = j / K, k = j % K;
    float w = W[(size_t)k * N + n];
    __half h = __float2half(w);
    __half l = __float2half(w - __half2float(h));
    wh[off + j] = h;
    wl[off + j] = l;
}

// ---------------- layer 1 fused: dwconv(3ch) + mix(3->64) + lrelu + stats ---
__global__ __launch_bounds__(256) void l1_fused_kernel(
    const float* __restrict__ x, const float* __restrict__ kern,
    const float* __restrict__ W, const float* __restrict__ bias,
    __half* __restrict__ Y, float* __restrict__ sums)
{
    __shared__ float sW[3][64];
    __shared__ float sB[64];
    __shared__ float sK[3][16];
    __shared__ float sD[3][64];
    __shared__ float sSum[64], sSq[64];

    int b = blockIdx.y, oh = blockIdx.x;
    int tid = threadIdx.x;

    if (tid < 192) sW[tid / 64][tid % 64] = W[tid];
    if (tid < 64) { sB[tid] = bias[tid]; sSum[tid] = 0.f; sSq[tid] = 0.f; }
    if (tid >= 192 && tid < 240) { int q = tid - 192; sK[q / 16][q % 16] = kern[(size_t)b * 48 + q]; }
    __syncthreads();

    if (tid < 192) {
        int c = tid / 64, ow = tid % 64;
        const float* xp = x + ((size_t)b * 3 + c) * 16384;
        float a = 0.f;
#pragma unroll
        for (int kh = 0; kh < 4; kh++) {
            int ih = oh * 2 - 1 + kh;
            if ((unsigned)ih < 128u) {
#pragma unroll
                for (int kw = 0; kw < 4; kw++) {
                    int iw = ow * 2 - 1 + kw;
                    if ((unsigned)iw < 128u) a += xp[ih * 128 + iw] * sK[c][kh * 4 + kw];
                }
            }
        }
        sD[c][ow] = a;
    }
    __syncthreads();

    int tx = tid & 63, py = tid >> 6;
    float w0 = sW[0][tx], w1 = sW[1][tx], w2 = sW[2][tx], bb = sB[tx];
    float s = 0.f, q = 0.f;
#pragma unroll
    for (int pix = py; pix < 64; pix += 4) {
        float v = fmaf(sD[0][pix], w0, fmaf(sD[1][pix], w1, fmaf(sD[2][pix], w2, bb)));
        v = v > 0.f ? v : 0.2f * v;
        Y[(((size_t)b * 64 + oh) * 64 + pix) * 64 + tx] = __float2half(v);
        s += v; q += v * v;
    }
    atomicAdd(&sSum[tx], s);
    atomicAdd(&sSq[tx], q);
    __syncthreads();
    if (tid < 64) { atomicAdd(&sums[tid], sSum[tid]); atomicAdd(&sums[64 + tid], sSq[tid]); }
}

// ---------------- dwconv v5: 2x2 blocking, fp16 LDG.64 in/out, BN fold ------
template<int KS, int C, int Hin, int Win, int Hout, int Wout, int Stride, int Pad>
__global__ __launch_bounds__((C / 4) * ((Wout + 1) / 2)) void dwconv_v5_kernel(
    const __half* __restrict__ Yin, const float* __restrict__ sums,
    const float* __restrict__ bn_g, const float* __restrict__ bn_b, float invCnt,
    const float* __restrict__ kern, __half* __restrict__ outF)
{
    constexpr int KK = KS * KS;
    constexpr int CG = C / 4;
    constexpr int W2 = (Wout + 1) / 2;
    constexpr int NT = CG * W2;
    constexpr int SPAN = KS + Stride;            // input span covering 2 outputs
    __shared__ __align__(16) float sW[KK][C];
    __shared__ __align__(16) float sSc[C], sSh[C];

    const int b = blockIdx.y, rp = blockIdx.x;
    const int tid = threadIdx.x;

    for (int c = tid; c < C; c += NT) {
        float mean = sums[c] * invCnt;
        float var  = sums[C + c] * invCnt - mean * mean;
        float sc = bn_g[c] * rsqrtf(var + 1e-5f);
        sSc[c] = sc;
        sSh[c] = bn_b[c] - mean * sc;
    }
    const float* kb = kern + (size_t)b * C * KK;
    for (int idx = tid; idx < C * KK; idx += NT) {
        int c = idx / KK, tap = idx % KK;
        sW[tap][c] = kb[idx];
    }
    __syncthreads();

    const int cg = tid % CG, wq = tid / CG;
    const int c = cg * 4;
    const int oh0 = 2 * rp, ow0 = 2 * wq;
    const int ihB = oh0 * Stride - Pad;
    const int iwB = ow0 * Stride - Pad;
    const float4 sc = *(const float4*)&sSc[c];
    const float4 sh = *(const float4*)&sSh[c];

    float4 acc[2][2];
#pragma unroll
    for (int oy = 0; oy < 2; oy++)
#pragma unroll
        for (int ox = 0; ox < 2; ox++) acc[oy][ox] = make_float4(0.f, 0.f, 0.f, 0.f);

#pragma unroll
    for (int rr = 0; rr < SPAN; rr++) {
        int ih = ihB + rr;
        if ((unsigned)ih >= (unsigned)Hin) continue;
        float4 v[SPAN];
#pragma unroll
        for (int cc = 0; cc < SPAN; cc++) {
            int iw = iwB + cc;
            if ((unsigned)iw < (unsigned)Win) {
                uint2 raw = *(const uint2*)&Yin[(((size_t)b * Hin + ih) * Win + iw) * C + c];
                float2 f0 = __half22float2(*(__half2*)&raw.x);
                float2 f1 = __half22float2(*(__half2*)&raw.y);
                v[cc].x = fmaf(f0.x, sc.x, sh.x);
                v[cc].y = fmaf(f0.y, sc.y, sh.y);
                v[cc].z = fmaf(f1.x, sc.z, sh.z);
                v[cc].w = fmaf(f1.y, sc.w, sh.w);
            } else {
                v[cc] = make_float4(0.f, 0.f, 0.f, 0.f);
            }
        }
#pragma unroll
        for (int oy = 0; oy < 2; oy++) {
            int kh = rr - oy * Stride;
            if (kh < 0 || kh >= KS) continue;
#pragma unroll
            for (int kw = 0; kw < KS; kw++) {
                float4 w = *(const float4*)&sW[kh * KS + kw][c];
#pragma unroll
                for (int ox = 0; ox < 2; ox++) {
                    float4 vv = v[kw + ox * Stride];
                    acc[oy][ox].x += vv.x * w.x;
                    acc[oy][ox].y += vv.y * w.y;
                    acc[oy][ox].z += vv.z * w.z;
                    acc[oy][ox].w += vv.w * w.w;
                }
            }
        }
    }

#pragma unroll
    for (int oy = 0; oy < 2; oy++) {
        int oh = oh0 + oy;
        if (oh >= Hout) break;
#pragma unroll
        for (int ox = 0; ox < 2; ox++) {
            int ow = ow0 + ox;
            if (ow >= Wout) break;
            float4 a = acc[oy][ox];
            size_t o = (((size_t)b * Hout + oh) * Wout + ow) * C + c;
            __half2 p0 = __floats2half2_rn(a.x, a.y);
            __half2 p1 = __floats2half2_rn(a.z, a.w);
            uint2 pk;
            pk.x = *(unsigned*)&p0;
            pk.y = *(unsigned*)&p1;
            *(uint2*)&outF[o] = pk;
        }
    }
}

// ---------------- channel mixer GEMM v5: BM=64 tile, 3 CTAs/SM --------------
// A: M x K fp16 row-major. Wh/Wl: N x K fp16 row-major.
// Tile: 64 x 128. 8 warps = 2(M) x 4(N). Per-thread acc 2x4x4 = 32 regs.
// MODE 0: Y fp16 row-major + stats.  MODE 1: fp32 NCHW sigmoid output.
template<int MODE>
__global__ __launch_bounds__(256, 3) void mix_mma5_kernel(
    const __half* __restrict__ A,
    const __half* __restrict__ Wh, const __half* __restrict__ Wl,
    const float* __restrict__ bias, __half* __restrict__ Yh, float* __restrict__ Yf,
    float* __restrict__ sums, int M, int N, int K, int spatial)
{
    extern __shared__ unsigned smemU[];          // 2 stages x (A 1280 + Bh 2560 + Bl 2560) u32
    __shared__ float sSum[128], sSq[128];

    const int tid  = threadIdx.x;
    const int wid  = tid >> 5, lane = tid & 31;
    const int g    = lane >> 2, tig = lane & 3;
    const int wm   = (wid >> 2) * 32;            // 2 warp-rows x 32 rows
    const int wn   = (wid & 3) * 32;             // 4 warp-cols x 32 cols
    const int m0   = blockIdx.x * 64, n0 = blockIdx.y * 128;

    if (MODE == 0) {
        if (tid < 128) { sSum[tid] = 0.f; sSq[tid] = 0.f; }
    }

    float acc[2][4][4];
#pragma unroll
    for (int mi = 0; mi < 2; mi++)
#pragma unroll
        for (int ni = 0; ni < 4; ni++)
#pragma unroll
            for (int r = 0; r < 4; r++) acc[mi][ni][r] = 0.f;

    auto load_stage = [&](int kt, int s) {
        unsigned* base = smemU + s * 6400;
        const int k0 = kt * 32;
#pragma unroll
        for (int v = 0; v < 5; v++) {
            int cid = tid + 256 * v;
            if (cid < 256) {                      // A: 64 rows x 4 chunks
                int r = cid >> 2, ch = cid & 3;
                cp16(base + r * 20 + ch * 4, A + (size_t)(m0 + r) * K + k0 + ch * 8);
            } else if (cid < 768) {               // Wh: 128 rows x 4 chunks
                int i = cid - 256;
                int r = i >> 2, ch = i & 3;
                cp16(base + 1280 + r * 20 + ch * 4, Wh + (size_t)(n0 + r) * K + k0 + ch * 8);
            } else {                              // Wl
                int i = cid - 768;
                int r = i >> 2, ch = i & 3;
                cp16(base + 3840 + r * 20 + ch * 4, Wl + (size_t)(n0 + r) * K + k0 + ch * 8);
            }
        }
    };

    const int nk = K / 32;
    load_stage(0, 0);
    CP_COMMIT();

    for (int kt = 0; kt < nk; kt++) {
        if (kt + 1 < nk) {
            load_stage(kt + 1, (kt + 1) & 1);
            CP_COMMIT();
            CP_WAIT(1);
        } else {
            CP_WAIT(0);
        }
        __syncthreads();

        unsigned* base = smemU + (kt & 1) * 6400;
        unsigned (*As_)[20] = (unsigned(*)[20])(base);
        unsigned (*Bh_)[20] = (unsigned(*)[20])(base + 1280);
        unsigned (*Bl_)[20] = (unsigned(*)[20])(base + 3840);

#pragma unroll
        for (int s = 0; s < 2; s++) {
            unsigned ah[2][4], bh[4][2], bl[4][2];
#pragma unroll
            for (int mi = 0; mi < 2; mi++) {
                int r0 = wm + 16 * mi + g, r1 = r0 + 8;
                int c0 = 8 * s + tig;
                ah[mi][0] = As_[r0][c0];     ah[mi][1] = As_[r1][c0];
                ah[mi][2] = As_[r0][c0 + 4]; ah[mi][3] = As_[r1][c0 + 4];
            }
#pragma unroll
            for (int ni = 0; ni < 4; ni++) {
                int n = wn + 8 * ni + g;
                int c0 = 8 * s + tig;
                bh[ni][0] = Bh_[n][c0]; bh[ni][1] = Bh_[n][c0 + 4];
                bl[ni][0] = Bl_[n][c0]; bl[ni][1] = Bl_[n][c0 + 4];
            }
#pragma unroll
            for (int mi = 0; mi < 2; mi++)
#pragma unroll
                for (int ni = 0; ni < 4; ni++) {
                    mma_f16(acc[mi][ni], ah[mi][0], ah[mi][1], ah[mi][2], ah[mi][3],
                            bh[ni][0], bh[ni][1]);
                    mma_f16(acc[mi][ni], ah[mi][0], ah[mi][1], ah[mi][2], ah[mi][3],
                            bl[ni][0], bl[ni][1]);
                }
        }
        __syncthreads();
    }

    float2 bv[4];
#pragma unroll
    for (int ni = 0; ni < 4; ni++)
        bv[ni] = *(const float2*)(bias + n0 + wn + 8 * ni + 2 * tig);

    if (MODE == 0) {
        float cs[4][2], cq[4][2];
#pragma unroll
        for (int ni = 0; ni < 4; ni++) { cs[ni][0] = cs[ni][1] = 0.f; cq[ni][0] = cq[ni][1] = 0.f; }
#pragma unroll
        for (int mi = 0; mi < 2; mi++) {
            int r0 = m0 + wm + 16 * mi + g, r1 = r0 + 8;
#pragma unroll
            for (int ni = 0; ni < 4; ni++) {
                int n = n0 + wn + 8 * ni + 2 * tig;
                float v0 = acc[mi][ni][0] + bv[ni].x;
                float v1 = acc[mi][ni][1] + bv[ni].y;
                float v2 = acc[mi][ni][2] + bv[ni].x;
                float v3 = acc[mi][ni][3] + bv[ni].y;
                v0 = v0 > 0.f ? v0 : 0.2f * v0;
                v1 = v1 > 0.f ? v1 : 0.2f * v1;
                v2 = v2 > 0.f ? v2 : 0.2f * v2;
                v3 = v3 > 0.f ? v3 : 0.2f * v3;
                *(__half2*)(Yh + (size_t)r0 * N + n) = __floats2half2_rn(v0, v1);
                *(__half2*)(Yh + (size_t)r1 * N + n) = __floats2half2_rn(v2, v3);
                cs[ni][0] += v0 + v2; cs[ni][1] += v1 + v3;
                cq[ni][0] += v0 * v0 + v2 * v2; cq[ni][1] += v1 * v1 + v3 * v3;
            }
        }
#pragma unroll
        for (int ni = 0; ni < 4; ni++) {
            int n = wn + 8 * ni + 2 * tig;
            atomicAdd(&sSum[n],     cs[ni][0]);
            atomicAdd(&sSum[n + 1], cs[ni][1]);
            atomicAdd(&sSq[n],      cq[ni][0]);
            atomicAdd(&sSq[n + 1],  cq[ni][1]);
        }
        __syncthreads();
        if (tid < 128) {
            atomicAdd(&sums[n0 + tid],     sSum[tid]);
            atomicAdd(&sums[N + n0 + tid], sSq[tid]);
        }
    } else {
#pragma unroll
        for (int mi = 0; mi < 2; mi++) {
            int r0 = m0 + wm + 16 * mi + g, r1 = r0 + 8;
            int b0i = r0 / spatial, p0 = r0 % spatial;
            int b1i = r1 / spatial, p1 = r1 % spatial;
#pragma unroll
            for (int ni = 0; ni < 4; ni++) {
                int n = n0 + wn + 8 * ni + 2 * tig;
                float v0 = acc[mi][ni][0] + bv[ni].x;
                float v1 = acc[mi][ni][1] + bv[ni].y;
                float v2 = acc[mi][ni][2] + bv[ni].x;
                float v3 = acc[mi][ni][3] + bv[ni].y;
                v0 = 1.f / (1.f + expf(-v0));
                v1 = 1.f / (1.f + expf(-v1));
                v2 = 1.f / (1.f + expf(-v2));
                v3 = 1.f / (1.f + expf(-v3));
                Yf[((size_t)b0i * N + n)     * spatial + p0] = v0;
                Yf[((size_t)b0i * N + n + 1) * spatial + p0] = v1;
                Yf[((size_t)b1i * N + n)     * spatial + p1] = v2;
                Yf[((size_t)b1i * N + n + 1) * spatial + p1] = v3;
            }
        }
    }
}

__global__ void write_label_kernel(const int* __restrict__ label, float* __restrict__ out, int n)
{
    int i = threadIdx.x;
    if (i < n) out[i] = (float)label[i];
}

// ---------------- launcher ---------------------------------------------------
extern "C" void kernel_launch(void* const* d_in, const int* in_sizes, int n_in,
                              void* d_out, int out_size)
{
    const float* input = (const float*)d_in[0];
    const int*   label = (const int*)d_in[1];
    const float* emb   = (const float*)d_in[2];
    const float* lw[5] = {(const float*)d_in[3], (const float*)d_in[5], (const float*)d_in[7],
                          (const float*)d_in[9], (const float*)d_in[11]};
    const float* lb[5] = {(const float*)d_in[4], (const float*)d_in[6], (const float*)d_in[8],
                          (const float*)d_in[10], (const float*)d_in[12]};
    const float* cmw[5] = {(const float*)d_in[13], (const float*)d_in[15], (const float*)d_in[17],
                           (const float*)d_in[19], (const float*)d_in[21]};
    const float* cmb[5] = {(const float*)d_in[14], (const float*)d_in[16], (const float*)d_in[18],
                           (const float*)d_in[20], (const float*)d_in[22]};
    const float* bng[4] = {(const float*)d_in[23], (const float*)d_in[25],
                           (const float*)d_in[27], (const float*)d_in[29]};
    const float* bnb[4] = {(const float*)d_in[24], (const float*)d_in[26],
                           (const float*)d_in[28], (const float*)d_in[30]};

    float *pK, *pSums;
    __half *pA, *pB, *pDwF, *pWH, *pWL;
    cudaGetSymbolAddress((void**)&pA,    g_actA);
    cudaGetSymbolAddress((void**)&pB,    g_actB);
    cudaGetSymbolAddress((void**)&pDwF,  g_dwF);
    cudaGetSymbolAddress((void**)&pWH,   g_wspH);
    cudaGetSymbolAddress((void**)&pWL,   g_wspL);
    cudaGetSymbolAddress((void**)&pK,    g_kern);
    cudaGetSymbolAddress((void**)&pSums, g_sums);

    float* out = (float*)d_out;

    const int SMEM = 51200;
    cudaFuncSetAttribute(mix_mma5_kernel<0>, cudaFuncAttributeMaxDynamicSharedMemorySize, SMEM);
    cudaFuncSetAttribute(mix_mma5_kernel<1>, cudaFuncAttributeMaxDynamicSharedMemorySize, SMEM);

    // ---------- prep: dyn kernels + zero sums; split mixer weights ----------
    prep_kernel<<<dim3(33, 128), 256>>>(label, emb, lw[0], lb[0], lw[1], lb[1],
                                        lw[2], lb[2], lw[3], lb[3], lw[4], lb[4],
                                        pK, pSums);
    wsplit_kernel<<<1696, 256>>>(cmw[1], cmw[2], cmw[3], cmw[4], pWH, pWL);

    // ---------- Layer 1 (fused): dwconv(3ch,128->64) + mix(3->64) ----------
    l1_fused_kernel<<<dim3(64, 128), 256>>>(input, pK + KOFF1, cmw[0], cmb[0], pA, pSums + SOFF1);

    // ---------- Layer 2 ----------
    {
        dwconv_v5_kernel<4, 64, 64, 64, 32, 32, 2, 1><<<dim3(16, 128), 16 * 16>>>(
            pA, pSums + SOFF1, bng[0], bnb[0], 1.f / (float)(128 * 64 * 64), pK + KOFF2, pDwF);
        int M = 128 * 32 * 32, N = 128, K = 64;
        mix_mma5_kernel<0><<<dim3(M / 64, N / 128), 256, SMEM>>>(
            pDwF, pWH + W2OFF, pWL + W2OFF, cmb[1], pB, nullptr, pSums + SOFF2, M, N, K, 0);
    }
    // ---------- Layer 3 ----------
    {
        dwconv_v5_kernel<3, 128, 32, 32, 16, 16, 2, 1><<<dim3(8, 128), 32 * 8>>>(
            pB, pSums + SOFF2, bng[1], bnb[1], 1.f / (float)(128 * 32 * 32), pK + KOFF3, pDwF);
        int M = 128 * 16 * 16, N = 256, K = 128;
        mix_mma5_kernel<0><<<dim3(M / 64, N / 128), 256, SMEM>>>(
            pDwF, pWH + W3OFF, pWL + W3OFF, cmb[2], pA, nullptr, pSums + SOFF3, M, N, K, 0);
    }
    // ---------- Layer 4 ----------
    {
        dwconv_v5_kernel<4, 256, 16, 16, 8, 8, 2, 1><<<dim3(4, 128), 64 * 4>>>(
            pA, pSums + SOFF3, bng[2], bnb[2], 1.f / (float)(128 * 16 * 16), pK + KOFF4, pDwF);
        int M = 128 * 8 * 8, N = 512, K = 256;
        mix_mma5_kernel<0><<<dim3(M / 64, N / 128), 256, SMEM>>>(
            pDwF, pWH + W4OFF, pWL + W4OFF, cmb[3], pB, nullptr, pSums + SOFF4, M, N, K, 0);
    }
    // ---------- Layer 5 ----------
    {
        dwconv_v5_kernel<2, 512, 8, 8, 7, 7, 1, 0><<<dim3(4, 128), 128 * 4>>>(
            pB, pSums + SOFF4, bng[3], bnb[3], 1.f / (float)(128 * 8 * 8), pK + KOFF5, pDwF);
        int M = 128 * 49, N = 512, K = 512;
        mix_mma5_kernel<1><<<dim3(M / 64, N / 128), 256, SMEM>>>(
            pDwF, pWH + W5OFF, pWL + W5OFF, cmb[4], nullptr, out, nullptr, M, N, K, 49);
    }
    // ---------- label tail ----------
    {
        long long zElems = 128LL * 512 * 49;
        long long tail = (long long)out_size - zElems;
        if (tail > 0) {
            int n = tail > 128 ? 128 : (int)tail;
            write_label_kernel<<<1, 128>>>(label, out + zElems, n);
        }
    }
}

// round 17
// speedup vs baseline: 1.2017x; 1.2017x over previous
#include <cuda_runtime.h>
#include <cuda_bf16.h>
#include <cuda_fp16.h>
#include <cstddef>

// ---------------- scratch (device globals; no allocation allowed) ----------
__device__ __half g_actA[33554432];               // mix/l1 outputs fp16 (NHWC)
__device__ __half g_actB[16777216];               // mix outputs fp16 (NHWC)
__device__ __half g_dwF[8388608];                 // dwconv out fp16 (M x K)
__device__ __half g_wspH[434176];                 // mixer weights fp16 (N x K)
__device__ float g_kern[1179648];                 // all 5 dyn kernel sets
__device__ float g_sums[2048];                    // per-layer sum/sumsq regions

// dyn-kernel region offsets (floats)
#define KOFF1 0
#define KOFF2 6144
#define KOFF3 137216
#define KOFF4 284672
#define KOFF5 808960
// BN sums region offsets
#define SOFF1 0
#define SOFF2 128
#define SOFF3 384
#define SOFF4 896
// weight region offsets (elements, N x K layout)
#define W2OFF 0
#define W3OFF 8192
#define W4OFF 40960
#define W5OFF 172032

// ---------------- helpers ----------------------------------------------------
__device__ __forceinline__ void mma_f16(float* c, unsigned a0, unsigned a1, unsigned a2,
                                        unsigned a3, unsigned b0, unsigned b1)
{
    asm volatile(
        "mma.sync.aligned.m16n8k16.row.col.f32.f16.f16.f32 "
        "{%0,%1,%2,%3}, {%4,%5,%6,%7}, {%8,%9}, {%0,%1,%2,%3};\n"
        : "+f"(c[0]), "+f"(c[1]), "+f"(c[2]), "+f"(c[3])
        : "r"(a0), "r"(a1), "r"(a2), "r"(a3), "r"(b0), "r"(b1));
}

__device__ __forceinline__ void cp16(void* dst, const void* src)
{
    unsigned d = (unsigned)__cvta_generic_to_shared(dst);
    asm volatile("cp.async.cg.shared.global [%0], [%1], 16;\n" :: "r"(d), "l"(src));
}
#define CP_COMMIT() asm volatile("cp.async.commit_group;\n" ::: "memory")
#define CP_WAIT(n)  asm volatile("cp.async.wait_group %0;\n" :: "n"(n) : "memory")

// ---------------- prep: all dyn kernels (tanh(e@W+b)) + zero sums -----------
__global__ void prep_kernel(const int* __restrict__ label, const float* __restrict__ emb,
                            const float* __restrict__ w1, const float* __restrict__ b1,
                            const float* __restrict__ w2, const float* __restrict__ b2,
                            const float* __restrict__ w3, const float* __restrict__ b3,
                            const float* __restrict__ w4, const float* __restrict__ b4,
                            const float* __restrict__ w5, const float* __restrict__ b5,
                            float* __restrict__ kern, float* __restrict__ sums)
{
    int b = blockIdx.y;
    int i = blockIdx.x * 256 + threadIdx.x;
    if (b == 0 && i < 1920) sums[i] = 0.f;

    const float* W; const float* bb; int ck, off, j;
    if (i < 48)            { W = w1; bb = b1; ck = 48;   off = KOFF1; j = i; }
    else if (i < 1072)     { W = w2; bb = b2; ck = 1024; off = KOFF2; j = i - 48; }
    else if (i < 2224)     { W = w3; bb = b3; ck = 1152; off = KOFF3; j = i - 1072; }
    else if (i < 6320)     { W = w4; bb = b4; ck = 4096; off = KOFF4; j = i - 2224; }
    else if (i < 8368)     { W = w5; bb = b5; ck = 2048; off = KOFF5; j = i - 6320; }
    else return;

    const float* e = emb + label[b] * 5;
    float a = bb[j];
#pragma unroll
    for (int t = 0; t < 5; t++) a += e[t] * W[t * ck + j];
    kern[off + (size_t)b * ck + j] = tanhf(a);
}

// ---------------- wsplit: mixer weights fp32 (K x N) -> fp16 (N x K) --------
__global__ void wsplit_kernel(const float* __restrict__ w2, const float* __restrict__ w3,
                              const float* __restrict__ w4, const float* __restrict__ w5,
                              __half* __restrict__ wh)
{
    int i = blockIdx.x * 256 + threadIdx.x;
    const float* W; int K, N, off, j;
    if (i < 8192)        { W = w2; K = 64;  N = 128; off = W2OFF; j = i; }
    else if (i < 40960)  { W = w3; K = 128; N = 256; off = W3OFF; j = i - 8192; }
    else if (i < 172032) { W = w4; K = 256; N = 512; off = W4OFF; j = i - 40960; }
    else if (i < 434176) { W = w5; K = 512; N = 512; off = W5OFF; j = i - 172032; }
    else return;
    int n = j / K, k = j % K;
    wh[off + j] = __float2half(W[(size_t)k * N + n]);
}

// ---------------- layer 1 fused: dwconv(3ch) + mix(3->64) + lrelu + stats ---
__global__ __launch_bounds__(256) void l1_fused_kernel(
    const float* __restrict__ x, const float* __restrict__ kern,
    const float* __restrict__ W, const float* __restrict__ bias,
    __half* __restrict__ Y, float* __restrict__ sums)
{
    __shared__ float sW[3][64];
    __shared__ float sB[64];
    __shared__ float sK[3][16];
    __shared__ float sD[3][64];
    __shared__ float sSum[64], sSq[64];

    int b = blockIdx.y, oh = blockIdx.x;
    int tid = threadIdx.x;

    if (tid < 192) sW[tid / 64][tid % 64] = W[tid];
    if (tid < 64) { sB[tid] = bias[tid]; sSum[tid] = 0.f; sSq[tid] = 0.f; }
    if (tid >= 192 && tid < 240) { int q = tid - 192; sK[q / 16][q % 16] = kern[(size_t)b * 48 + q]; }
    __syncthreads();

    if (tid < 192) {
        int c = tid / 64, ow = tid % 64;
        const float* xp = x + ((size_t)b * 3 + c) * 16384;
        float a = 0.f;
#pragma unroll
        for (int kh = 0; kh < 4; kh++) {
            int ih = oh * 2 - 1 + kh;
            if ((unsigned)ih < 128u) {
#pragma unroll
                for (int kw = 0; kw < 4; kw++) {
                    int iw = ow * 2 - 1 + kw;
                    if ((unsigned)iw < 128u) a += xp[ih * 128 + iw] * sK[c][kh * 4 + kw];
                }
            }
        }
        sD[c][ow] = a;
    }
    __syncthreads();

    int tx = tid & 63, py = tid >> 6;
    float w0 = sW[0][tx], w1 = sW[1][tx], w2 = sW[2][tx], bb = sB[tx];
    float s = 0.f, q = 0.f;
#pragma unroll
    for (int pix = py; pix < 64; pix += 4) {
        float v = fmaf(sD[0][pix], w0, fmaf(sD[1][pix], w1, fmaf(sD[2][pix], w2, bb)));
        v = v > 0.f ? v : 0.2f * v;
        Y[(((size_t)b * 64 + oh) * 64 + pix) * 64 + tx] = __float2half(v);
        s += v; q += v * v;
    }
    atomicAdd(&sSum[tx], s);
    atomicAdd(&sSq[tx], q);
    __syncthreads();
    if (tid < 64) { atomicAdd(&sums[tid], sSum[tid]); atomicAdd(&sums[64 + tid], sSq[tid]); }
}

// ---------------- dwconv v5: 2x2 blocking, fp16 LDG.64 in/out, BN fold ------
template<int KS, int C, int Hin, int Win, int Hout, int Wout, int Stride, int Pad>
__global__ __launch_bounds__((C / 4) * ((Wout + 1) / 2)) void dwconv_v5_kernel(
    const __half* __restrict__ Yin, const float* __restrict__ sums,
    const float* __restrict__ bn_g, const float* __restrict__ bn_b, float invCnt,
    const float* __restrict__ kern, __half* __restrict__ outF)
{
    constexpr int KK = KS * KS;
    constexpr int CG = C / 4;
    constexpr int W2 = (Wout + 1) / 2;
    constexpr int NT = CG * W2;
    constexpr int SPAN = KS + Stride;            // input span covering 2 outputs
    __shared__ __align__(16) float sW[KK][C];
    __shared__ __align__(16) float sSc[C], sSh[C];

    const int b = blockIdx.y, rp = blockIdx.x;
    const int tid = threadIdx.x;

    for (int c = tid; c < C; c += NT) {
        float mean = sums[c] * invCnt;
        float var  = sums[C + c] * invCnt - mean * mean;
        float sc = bn_g[c] * rsqrtf(var + 1e-5f);
        sSc[c] = sc;
        sSh[c] = bn_b[c] - mean * sc;
    }
    const float* kb = kern + (size_t)b * C * KK;
    for (int idx = tid; idx < C * KK; idx += NT) {
        int c = idx / KK, tap = idx % KK;
        sW[tap][c] = kb[idx];
    }
    __syncthreads();

    const int cg = tid % CG, wq = tid / CG;
    const int c = cg * 4;
    const int oh0 = 2 * rp, ow0 = 2 * wq;
    const int ihB = oh0 * Stride - Pad;
    const int iwB = ow0 * Stride - Pad;
    const float4 sc = *(const float4*)&sSc[c];
    const float4 sh = *(const float4*)&sSh[c];

    float4 acc[2][2];
#pragma unroll
    for (int oy = 0; oy < 2; oy++)
#pragma unroll
        for (int ox = 0; ox < 2; ox++) acc[oy][ox] = make_float4(0.f, 0.f, 0.f, 0.f);

#pragma unroll
    for (int rr = 0; rr < SPAN; rr++) {
        int ih = ihB + rr;
        if ((unsigned)ih >= (unsigned)Hin) continue;
        float4 v[SPAN];
#pragma unroll
        for (int cc = 0; cc < SPAN; cc++) {
            int iw = iwB + cc;
            if ((unsigned)iw < (unsigned)Win) {
                uint2 raw = *(const uint2*)&Yin[(((size_t)b * Hin + ih) * Win + iw) * C + c];
                float2 f0 = __half22float2(*(__half2*)&raw.x);
                float2 f1 = __half22float2(*(__half2*)&raw.y);
                v[cc].x = fmaf(f0.x, sc.x, sh.x);
                v[cc].y = fmaf(f0.y, sc.y, sh.y);
                v[cc].z = fmaf(f1.x, sc.z, sh.z);
                v[cc].w = fmaf(f1.y, sc.w, sh.w);
            } else {
                v[cc] = make_float4(0.f, 0.f, 0.f, 0.f);
            }
        }
#pragma unroll
        for (int oy = 0; oy < 2; oy++) {
            int kh = rr - oy * Stride;
            if (kh < 0 || kh >= KS) continue;
#pragma unroll
            for (int kw = 0; kw < KS; kw++) {
                float4 w = *(const float4*)&sW[kh * KS + kw][c];
#pragma unroll
                for (int ox = 0; ox < 2; ox++) {
                    float4 vv = v[kw + ox * Stride];
                    acc[oy][ox].x += vv.x * w.x;
                    acc[oy][ox].y += vv.y * w.y;
                    acc[oy][ox].z += vv.z * w.z;
                    acc[oy][ox].w += vv.w * w.w;
                }
            }
        }
    }

#pragma unroll
    for (int oy = 0; oy < 2; oy++) {
        int oh = oh0 + oy;
        if (oh >= Hout) break;
#pragma unroll
        for (int ox = 0; ox < 2; ox++) {
            int ow = ow0 + ox;
            if (ow >= Wout) break;
            float4 a = acc[oy][ox];
            size_t o = (((size_t)b * Hout + oh) * Wout + ow) * C + c;
            __half2 p0 = __floats2half2_rn(a.x, a.y);
            __half2 p1 = __floats2half2_rn(a.z, a.w);
            uint2 pk;
            pk.x = *(unsigned*)&p0;
            pk.y = *(unsigned*)&p1;
            *(uint2*)&outF[o] = pk;
        }
    }
}

// ---------------- channel mixer GEMM v6: pure fp16 MMA, cp.async pipeline ---
// A: M x K fp16 row-major. W: N x K fp16 row-major. One MMA per acc per step.
// MODE 0: Y fp16 row-major + stats.  MODE 1: fp32 NCHW sigmoid output.
template<int MODE>
__global__ __launch_bounds__(256, 2) void mix_mma6_kernel(
    const __half* __restrict__ A, const __half* __restrict__ Wt,
    const float* __restrict__ bias, __half* __restrict__ Yh, float* __restrict__ Yf,
    float* __restrict__ sums, int M, int N, int K, int spatial)
{
    extern __shared__ unsigned smemU[];          // 2 stages x 2 arrays x 128 x 20 u32
    __shared__ float sSum[128], sSq[128];

    const int tid  = threadIdx.x;
    const int wid  = tid >> 5, lane = tid & 31;
    const int g    = lane >> 2, tig = lane & 3;
    const int wm   = (wid >> 2) * 64;
    const int wn   = (wid & 3) * 32;
    const int m0   = blockIdx.x * 128, n0 = blockIdx.y * 128;

    if (MODE == 0) {
        if (tid < 128) { sSum[tid] = 0.f; sSq[tid] = 0.f; }
    }

    float acc[4][4][4];
#pragma unroll
    for (int mi = 0; mi < 4; mi++)
#pragma unroll
        for (int ni = 0; ni < 4; ni++)
#pragma unroll
            for (int r = 0; r < 4; r++) acc[mi][ni][r] = 0.f;

    auto load_stage = [&](int kt, int s) {
        unsigned* base = smemU + s * 5120;
        const int k0 = kt * 32;
#pragma unroll
        for (int v = 0; v < 4; v++) {
            int cid = tid + 256 * v;
            int arr = cid >> 9;                  // 0:A 1:W (constant per v)
            int r   = (cid >> 2) & 127;
            int ch  = cid & 3;
            const __half* src = (arr == 0) ? A  + (size_t)(m0 + r) * K + k0 + ch * 8
                                           : Wt + (size_t)(n0 + r) * K + k0 + ch * 8;
            cp16(base + arr * 2560 + r * 20 + ch * 4, src);
        }
    };

    const int nk = K / 32;
    load_stage(0, 0);
    CP_COMMIT();

    for (int kt = 0; kt < nk; kt++) {
        if (kt + 1 < nk) {
            load_stage(kt + 1, (kt + 1) & 1);
            CP_COMMIT();
            CP_WAIT(1);
        } else {
            CP_WAIT(0);
        }
        __syncthreads();

        unsigned* base = smemU + (kt & 1) * 5120;
        unsigned (*As_)[20] = (unsigned(*)[20])(base);
        unsigned (*Bs_)[20] = (unsigned(*)[20])(base + 2560);

#pragma unroll
        for (int s = 0; s < 2; s++) {
            unsigned ah[4][4], bh[4][2];
#pragma unroll
            for (int mi = 0; mi < 4; mi++) {
                int r0 = wm + 16 * mi + g, r1 = r0 + 8;
                int c0 = 8 * s + tig;
                ah[mi][0] = As_[r0][c0];     ah[mi][1] = As_[r1][c0];
                ah[mi][2] = As_[r0][c0 + 4]; ah[mi][3] = As_[r1][c0 + 4];
            }
#pragma unroll
            for (int ni = 0; ni < 4; ni++) {
                int n = wn + 8 * ni + g;
                int c0 = 8 * s + tig;
                bh[ni][0] = Bs_[n][c0]; bh[ni][1] = Bs_[n][c0 + 4];
            }
#pragma unroll
            for (int mi = 0; mi < 4; mi++)
#pragma unroll
                for (int ni = 0; ni < 4; ni++)
                    mma_f16(acc[mi][ni], ah[mi][0], ah[mi][1], ah[mi][2], ah[mi][3],
                            bh[ni][0], bh[ni][1]);
        }
        __syncthreads();
    }

    float2 bv[4];
#pragma unroll
    for (int ni = 0; ni < 4; ni++)
        bv[ni] = *(const float2*)(bias + n0 + wn + 8 * ni + 2 * tig);

    if (MODE == 0) {
        float cs[4][2], cq[4][2];
#pragma unroll
        for (int ni = 0; ni < 4; ni++) { cs[ni][0] = cs[ni][1] = 0.f; cq[ni][0] = cq[ni][1] = 0.f; }
#pragma unroll
        for (int mi = 0; mi < 4; mi++) {
            int r0 = m0 + wm + 16 * mi + g, r1 = r0 + 8;
#pragma unroll
            for (int ni = 0; ni < 4; ni++) {
                int n = n0 + wn + 8 * ni + 2 * tig;
                float v0 = acc[mi][ni][0] + bv[ni].x;
                float v1 = acc[mi][ni][1] + bv[ni].y;
                float v2 = acc[mi][ni][2] + bv[ni].x;
                float v3 = acc[mi][ni][3] + bv[ni].y;
                v0 = v0 > 0.f ? v0 : 0.2f * v0;
                v1 = v1 > 0.f ? v1 : 0.2f * v1;
                v2 = v2 > 0.f ? v2 : 0.2f * v2;
                v3 = v3 > 0.f ? v3 : 0.2f * v3;
                *(__half2*)(Yh + (size_t)r0 * N + n) = __floats2half2_rn(v0, v1);
                *(__half2*)(Yh + (size_t)r1 * N + n) = __floats2half2_rn(v2, v3);
                cs[ni][0] += v0 + v2; cs[ni][1] += v1 + v3;
                cq[ni][0] += v0 * v0 + v2 * v2; cq[ni][1] += v1 * v1 + v3 * v3;
            }
        }
#pragma unroll
        for (int ni = 0; ni < 4; ni++) {
            int n = wn + 8 * ni + 2 * tig;
            atomicAdd(&sSum[n],     cs[ni][0]);
            atomicAdd(&sSum[n + 1], cs[ni][1]);
            atomicAdd(&sSq[n],      cq[ni][0]);
            atomicAdd(&sSq[n + 1],  cq[ni][1]);
        }
        __syncthreads();
        if (tid < 128) {
            atomicAdd(&sums[n0 + tid],     sSum[tid]);
            atomicAdd(&sums[N + n0 + tid], sSq[tid]);
        }
    } else {
#pragma unroll
        for (int mi = 0; mi < 4; mi++) {
            int r0 = m0 + wm + 16 * mi + g, r1 = r0 + 8;
            int b0i = r0 / spatial, p0 = r0 % spatial;
            int b1i = r1 / spatial, p1 = r1 % spatial;
#pragma unroll
            for (int ni = 0; ni < 4; ni++) {
                int n = n0 + wn + 8 * ni + 2 * tig;
                float v0 = acc[mi][ni][0] + bv[ni].x;
                float v1 = acc[mi][ni][1] + bv[ni].y;
                float v2 = acc[mi][ni][2] + bv[ni].x;
                float v3 = acc[mi][ni][3] + bv[ni].y;
                v0 = 1.f / (1.f + expf(-v0));
                v1 = 1.f / (1.f + expf(-v1));
                v2 = 1.f / (1.f + expf(-v2));
                v3 = 1.f / (1.f + expf(-v3));
                Yf[((size_t)b0i * N + n)     * spatial + p0] = v0;
                Yf[((size_t)b0i * N + n + 1) * spatial + p0] = v1;
                Yf[((size_t)b1i * N + n)     * spatial + p1] = v2;
                Yf[((size_t)b1i * N + n + 1) * spatial + p1] = v3;
            }
        }
    }
}

__global__ void write_label_kernel(const int* __restrict__ label, float* __restrict__ out, int n)
{
    int i = threadIdx.x;
    if (i < n) out[i] = (float)label[i];
}

// ---------------- launcher ---------------------------------------------------
extern "C" void kernel_launch(void* const* d_in, const int* in_sizes, int n_in,
                              void* d_out, int out_size)
{
    const float* input = (const float*)d_in[0];
    const int*   label = (const int*)d_in[1];
    const float* emb   = (const float*)d_in[2];
    const float* lw[5] = {(const float*)d_in[3], (const float*)d_in[5], (const float*)d_in[7],
                          (const float*)d_in[9], (const float*)d_in[11]};
    const float* lb[5] = {(const float*)d_in[4], (const float*)d_in[6], (const float*)d_in[8],
                          (const float*)d_in[10], (const float*)d_in[12]};
    const float* cmw[5] = {(const float*)d_in[13], (const float*)d_in[15], (const float*)d_in[17],
                           (const float*)d_in[19], (const float*)d_in[21]};
    const float* cmb[5] = {(const float*)d_in[14], (const float*)d_in[16], (const float*)d_in[18],
                           (const float*)d_in[20], (const float*)d_in[22]};
    const float* bng[4] = {(const float*)d_in[23], (const float*)d_in[25],
                           (const float*)d_in[27], (const float*)d_in[29]};
    const float* bnb[4] = {(const float*)d_in[24], (const float*)d_in[26],
                           (const float*)d_in[28], (const float*)d_in[30]};

    float *pK, *pSums;
    __half *pA, *pB, *pDwF, *pWH;
    cudaGetSymbolAddress((void**)&pA,    g_actA);
    cudaGetSymbolAddress((void**)&pB,    g_actB);
    cudaGetSymbolAddress((void**)&pDwF,  g_dwF);
    cudaGetSymbolAddress((void**)&pWH,   g_wspH);
    cudaGetSymbolAddress((void**)&pK,    g_kern);
    cudaGetSymbolAddress((void**)&pSums, g_sums);

    float* out = (float*)d_out;

    const int SMEM = 40960;
    cudaFuncSetAttribute(mix_mma6_kernel<0>, cudaFuncAttributeMaxDynamicSharedMemorySize, SMEM);
    cudaFuncSetAttribute(mix_mma6_kernel<1>, cudaFuncAttributeMaxDynamicSharedMemorySize, SMEM);

    // ---------- prep: dyn kernels + zero sums; convert mixer weights ----------
    prep_kernel<<<dim3(33, 128), 256>>>(label, emb, lw[0], lb[0], lw[1], lb[1],
                                        lw[2], lb[2], lw[3], lb[3], lw[4], lb[4],
                                        pK, pSums);
    wsplit_kernel<<<1696, 256>>>(cmw[1], cmw[2], cmw[3], cmw[4], pWH);

    // ---------- Layer 1 (fused): dwconv(3ch,128->64) + mix(3->64) ----------
    l1_fused_kernel<<<dim3(64, 128), 256>>>(input, pK + KOFF1, cmw[0], cmb[0], pA, pSums + SOFF1);

    // ---------- Layer 2 ----------
    {
        dwconv_v5_kernel<4, 64, 64, 64, 32, 32, 2, 1><<<dim3(16, 128), 16 * 16>>>(
            pA, pSums + SOFF1, bng[0], bnb[0], 1.f / (float)(128 * 64 * 64), pK + KOFF2, pDwF);
        int M = 128 * 32 * 32, N = 128, K = 64;
        mix_mma6_kernel<0><<<dim3(M / 128, N / 128), 256, SMEM>>>(
            pDwF, pWH + W2OFF, cmb[1], pB, nullptr, pSums + SOFF2, M, N, K, 0);
    }
    // ---------- Layer 3 ----------
    {
        dwconv_v5_kernel<3, 128, 32, 32, 16, 16, 2, 1><<<dim3(8, 128), 32 * 8>>>(
            pB, pSums + SOFF2, bng[1], bnb[1], 1.f / (float)(128 * 32 * 32), pK + KOFF3, pDwF);
        int M = 128 * 16 * 16, N = 256, K = 128;
        mix_mma6_kernel<0><<<dim3(M / 128, N / 128), 256, SMEM>>>(
            pDwF, pWH + W3OFF, cmb[2], pA, nullptr, pSums + SOFF3, M, N, K, 0);
    }
    // ---------- Layer 4 ----------
    {
        dwconv_v5_kernel<4, 256, 16, 16, 8, 8, 2, 1><<<dim3(4, 128), 64 * 4>>>(
            pA, pSums + SOFF3, bng[2], bnb[2], 1.f / (float)(128 * 16 * 16), pK + KOFF4, pDwF);
        int M = 128 * 8 * 8, N = 512, K = 256;
        mix_mma6_kernel<0><<<dim3(M / 128, N / 128), 256, SMEM>>>(
            pDwF, pWH + W4OFF, cmb[3], pB, nullptr, pSums + SOFF4, M, N, K, 0);
    }
    // ---------- Layer 5 ----------
    {
        dwconv_v5_kernel<2, 512, 8, 8, 7, 7, 1, 0><<<dim3(4, 128), 128 * 4>>>(
            pB, pSums + SOFF4, bng[3], bnb[3], 1.f / (float)(128 * 8 * 8), pK + KOFF5, pDwF);
        int M = 128 * 49, N = 512, K = 512;
        mix_mma6_kernel<1><<<dim3(M / 128, N / 128), 256, SMEM>>>(
            pDwF, pWH + W5OFF, cmb[4], nullptr, out, nullptr, M, N, K, 49);
    }
    // ---------- label tail ----------
    {
        long long zElems = 128LL * 512 * 49;
        long long tail = (long long)out_size - zElems;
        if (tail > 0) {
            int n = tail > 128 ? 128 : (int)tail;
            write_label_kernel<<<1, 128>>>(label, out + zElems, n);
        }
    }
}